// round 1
// baseline (speedup 1.0000x reference)
#include <cuda_runtime.h>
#include <math.h>

#define TPB 256

// Pre-transposed weights: g_WT[w][k][d] = W_w[d][k]  (w: 0=Wq 1=Wk 2=Wv 3=Theta)
__device__ float g_WT[4][128][128];

__device__ __forceinline__ float4 ld4(const float* p) {
    return *reinterpret_cast<const float4*>(p);
}
__device__ __forceinline__ void st4(float* p, float a, float b, float c, float d) {
    *reinterpret_cast<float4*>(p) = make_float4(a, b, c, d);
}

__global__ void transpose_weights_k(const float* __restrict__ Wq, const float* __restrict__ Wk,
                                    const float* __restrict__ Wv, const float* __restrict__ Th) {
    const float* W = (blockIdx.x == 0) ? Wq : (blockIdx.x == 1) ? Wk : (blockIdx.x == 2) ? Wv : Th;
    for (int idx = threadIdx.x; idx < 128 * 128; idx += blockDim.x) {
        int d = idx >> 7, k = idx & 127;
        g_WT[blockIdx.x][k][d] = W[idx];
    }
}

// -------- shared memory layout (float offsets) --------
#define OZ     0        // Z   [32][128]
#define OQ     4096     // Q   [32][128]   (later reused for spatial)
#define OKK    8192     // K   [32][132]   (later reused for y pre-LN)
#define OV     12416    // V   [32][128]
#define OWU    16512    // union: W k-tile [32][128]=4096  /  full W1 [32][260]=8320
#define OHQ    24832    // hq  [32][32]
#define OHKT   25856    // hk transposed [j][n] [32][32]
#define OLOG   26880    // logits/alpha [32][33]
#define OB1    27936    // 32
#define OW2    27968    // 32
#define OWF    28000    // 8 (W_fuse padded)
#define OGAM   28008    // 128
#define OBET   28136    // 128
#define OMSK   28264    // 32 (mask row as float 0/1)
#define OSC    28296    // [0]=phys_weight [1]=prior_weight [2]=b2
#define SMEMF  28304    // 113216 bytes

// out[32 x 128] = sIn[32 x 128] @ gW(k-major)[128 x 128], per-thread 4x4 block
__device__ __forceinline__ void gemm32(const float* __restrict__ sIn, const float* __restrict__ gW,
                                       float* __restrict__ sWt, int tid, float acc[4][4]) {
    const int warp = tid >> 5, lane = tid & 31;
    const int r0 = warp << 2, c0 = lane << 2;
#pragma unroll
    for (int i = 0; i < 4; i++)
#pragma unroll
        for (int j = 0; j < 4; j++) acc[i][j] = 0.f;

    for (int kt = 0; kt < 4; kt++) {
        __syncthreads();  // previous tile fully consumed
        {
            const float4* src = reinterpret_cast<const float4*>(gW + kt * 32 * 128);
            float4* dst = reinterpret_cast<float4*>(sWt);
#pragma unroll
            for (int it = 0; it < 4; it++) dst[tid + it * TPB] = src[tid + it * TPB];
        }
        __syncthreads();
        const float* zin = sIn + kt * 32;
#pragma unroll
        for (int kk = 0; kk < 32; kk += 4) {
            float4 z0 = ld4(zin + (r0 + 0) * 128 + kk);
            float4 z1 = ld4(zin + (r0 + 1) * 128 + kk);
            float4 z2 = ld4(zin + (r0 + 2) * 128 + kk);
            float4 z3 = ld4(zin + (r0 + 3) * 128 + kk);
#pragma unroll
            for (int u = 0; u < 4; u++) {
                float4 wv = ld4(sWt + (kk + u) * 128 + c0);
                float a[4];
                if (u == 0)      { a[0] = z0.x; a[1] = z1.x; a[2] = z2.x; a[3] = z3.x; }
                else if (u == 1) { a[0] = z0.y; a[1] = z1.y; a[2] = z2.y; a[3] = z3.y; }
                else if (u == 2) { a[0] = z0.z; a[1] = z1.z; a[2] = z2.z; a[3] = z3.z; }
                else             { a[0] = z0.w; a[1] = z1.w; a[2] = z2.w; a[3] = z3.w; }
#pragma unroll
                for (int i = 0; i < 4; i++) {
                    acc[i][0] = fmaf(a[i], wv.x, acc[i][0]);
                    acc[i][1] = fmaf(a[i], wv.y, acc[i][1]);
                    acc[i][2] = fmaf(a[i], wv.z, acc[i][2]);
                    acc[i][3] = fmaf(a[i], wv.w, acc[i][3]);
                }
            }
        }
    }
}

__global__ __launch_bounds__(TPB, 2)
void fused_gnn_kernel(const float* __restrict__ x, const float* __restrict__ edge,
                      const float* __restrict__ Aprior, const unsigned char* __restrict__ pmask,
                      const float* __restrict__ Wfuse, const float* __restrict__ W1,
                      const float* __restrict__ b1g, const float* __restrict__ W2g,
                      const float* __restrict__ b2g, const float* __restrict__ gammag,
                      const float* __restrict__ betag, const float* __restrict__ physw,
                      const float* __restrict__ priorw, float* __restrict__ out)
{
    extern __shared__ float sm[];
    const int tid = threadIdx.x;
    const int bt = blockIdx.x;
    const int b = bt >> 6, t = bt & 63;
    const int warp = tid >> 5, lane = tid & 31;
    const int r0 = warp << 2, c0 = lane << 2;

    // ---------------- Phase 0: stage Z and small tensors ----------------
#pragma unroll
    for (int it = 0; it < 4; it++) {
        int idx = tid + it * TPB;          // idx = n*32 + dgroup
        int n = idx >> 5, dg = idx & 31;
        reinterpret_cast<float4*>(sm + OZ)[idx] =
            ld4(x + ((((size_t)b * 32 + n) * 64 + t) * 128) + dg * 4);
    }
    if (tid < 32) {
        sm[OB1 + tid]  = b1g[tid];
        sm[OW2 + tid]  = W2g[tid];
        sm[OMSK + tid] = pmask[b * 32 + tid] ? 1.f : 0.f;
    } else if (tid < 40) {
        int i = tid - 32;
        sm[OWF + i] = (i < 5) ? Wfuse[i] : 0.f;
    } else if (tid == 40) {
        sm[OSC + 0] = physw[0];
    } else if (tid == 41) {
        sm[OSC + 1] = priorw[0];
    } else if (tid == 42) {
        sm[OSC + 2] = b2g[0];
    }
    if (tid >= 128) {
        sm[OGAM + tid - 128] = gammag[tid - 128];
        sm[OBET + tid - 128] = betag[tid - 128];
    }
    __syncthreads();

    // ---------------- Phase 1: Q, K, V GEMMs ----------------
    float acc[4][4];
    gemm32(sm + OZ, &g_WT[0][0][0], sm + OWU, tid, acc);
#pragma unroll
    for (int i = 0; i < 4; i++)
        st4(sm + OQ + (r0 + i) * 128 + c0, acc[i][0], acc[i][1], acc[i][2], acc[i][3]);

    gemm32(sm + OZ, &g_WT[1][0][0], sm + OWU, tid, acc);
#pragma unroll
    for (int i = 0; i < 4; i++)
        st4(sm + OKK + (r0 + i) * 132 + c0, acc[i][0], acc[i][1], acc[i][2], acc[i][3]);

    gemm32(sm + OZ, &g_WT[2][0][0], sm + OWU, tid, acc);
#pragma unroll
    for (int i = 0; i < 4; i++)
        st4(sm + OV + (r0 + i) * 128 + c0, acc[i][0], acc[i][1], acc[i][2], acc[i][3]);
    __syncthreads();

    // ---------------- Phase 2: stage W1 + content (kept in regs) ----------------
    for (int idx = tid; idx < 32 * 260; idx += TPB) sm[OWU + idx] = W1[idx];

    const int pn = tid >> 3, pm0 = (tid & 7) << 2;   // pair map: (n, m0..m0+3)
    float rc[4] = {0.f, 0.f, 0.f, 0.f};
    for (int dg = 0; dg < 32; dg++) {
        float4 q = ld4(sm + OQ + pn * 128 + dg * 4);
#pragma unroll
        for (int jj = 0; jj < 4; jj++) {
            float4 kv = ld4(sm + OKK + (pm0 + jj) * 132 + dg * 4);
            rc[jj] += q.x * kv.x + q.y * kv.y + q.z * kv.z + q.w * kv.w;
        }
    }
    __syncthreads();   // sW1 staged

    // ---------------- Phase 3: hq / hk ----------------
    {
        float aq[4] = {0.f, 0.f, 0.f, 0.f};
        float ak[4] = {0.f, 0.f, 0.f, 0.f};
        for (int dg = 0; dg < 32; dg++) {
            float4 qv = ld4(sm + OQ  + pn * 128 + dg * 4);
            float4 kv = ld4(sm + OKK + pn * 132 + dg * 4);
#pragma unroll
            for (int jj = 0; jj < 4; jj++) {
                float4 wq = ld4(sm + OWU + (pm0 + jj) * 260 + dg * 4);
                float4 wk = ld4(sm + OWU + (pm0 + jj) * 260 + 128 + dg * 4);
                aq[jj] += qv.x * wq.x + qv.y * wq.y + qv.z * wq.z + qv.w * wq.w;
                ak[jj] += kv.x * wk.x + kv.y * wk.y + kv.z * wk.z + kv.w * wk.w;
            }
        }
#pragma unroll
        for (int jj = 0; jj < 4; jj++) {
            sm[OHQ  + pn * 32 + pm0 + jj] = aq[jj];
            sm[OHKT + (pm0 + jj) * 32 + pn] = ak[jj];   // transposed: [j][n]
        }
    }
    __syncthreads();

    // ---------------- Phase 4: phys MLP + prior + logits ----------------
    {
        float4 e4[4];
#pragma unroll
        for (int jj = 0; jj < 4; jj++)
            e4[jj] = ld4(edge + ((((size_t)bt * 32 + pn) * 32) + pm0 + jj) * 4);

        float wf0 = sm[OWF + 0], wf1 = sm[OWF + 1], wf2 = sm[OWF + 2],
              wf3 = sm[OWF + 3], wf4 = sm[OWF + 4];
        float lpr[4];
#pragma unroll
        for (int jj = 0; jj < 4; jj++) {
            const float* ap = Aprior + ((((size_t)bt * 32 + pn) * 32) + pm0 + jj) * 5;
            float p = ap[0] * wf0 + ap[1] * wf1 + ap[2] * wf2 + ap[3] * wf3 + ap[4] * wf4;
            if (!isfinite(p)) p = 0.f;      // nan_to_num(nan=0, posinf=0, neginf=0)
            p = fmaxf(p, 0.f);              // clip at 0
            lpr[jj] = logf(p + 1e-6f);
        }

        float ph[4] = {0.f, 0.f, 0.f, 0.f};
        for (int j = 0; j < 32; j++) {
            float hb  = sm[OHQ + pn * 32 + j] + sm[OB1 + j];
            float w2v = sm[OW2 + j];
            const float* we = sm + OWU + j * 260 + 256;
            float we0 = we[0], we1 = we[1], we2 = we[2], we3 = we[3];
#pragma unroll
            for (int jj = 0; jj < 4; jj++) {
                float h = hb + sm[OHKT + j * 32 + pm0 + jj]
                        + e4[jj].x * we0 + e4[jj].y * we1
                        + e4[jj].z * we2 + e4[jj].w * we3;
                h = fmaxf(h, 0.f);
                ph[jj] = fmaf(h, w2v, ph[jj]);
            }
        }

        float pw = sm[OSC + 0], prw = sm[OSC + 1], b2v = sm[OSC + 2];
        float mn = sm[OMSK + pn];
#pragma unroll
        for (int jj = 0; jj < 4; jj++) {
            float lg = rc[jj] * 0.08838834764831845f       // content / sqrt(128)
                     + pw * (ph[jj] + b2v)
                     + prw * lpr[jj];
            if (mn != 0.f || sm[OMSK + pm0 + jj] != 0.f) lg = -1e9f;
            sm[OLOG + pn * 33 + pm0 + jj] = lg;
        }
    }
    __syncthreads();

    // ---------------- Phase 5: softmax over m (warp per 4 rows) ----------------
#pragma unroll
    for (int q = 0; q < 4; q++) {
        int n = r0 + q;
        float v = sm[OLOG + n * 33 + lane];
        float mx = v;
#pragma unroll
        for (int off = 16; off > 0; off >>= 1)
            mx = fmaxf(mx, __shfl_xor_sync(0xffffffffu, mx, off));
        float e = expf(v - mx);
        float s = e;
#pragma unroll
        for (int off = 16; off > 0; off >>= 1)
            s += __shfl_xor_sync(0xffffffffu, s, off);
        sm[OLOG + n * 33 + lane] = e / s;
    }
    __syncthreads();

    // ---------------- Phase 6: spatial = alpha @ V  (into sQ) ----------------
    {
        float sa[4][4];
#pragma unroll
        for (int i = 0; i < 4; i++)
#pragma unroll
            for (int j = 0; j < 4; j++) sa[i][j] = 0.f;
        for (int k = 0; k < 32; k++) {
            float4 vv = ld4(sm + OV + k * 128 + c0);
            float a0 = sm[OLOG + (r0 + 0) * 33 + k];
            float a1 = sm[OLOG + (r0 + 1) * 33 + k];
            float a2 = sm[OLOG + (r0 + 2) * 33 + k];
            float a3 = sm[OLOG + (r0 + 3) * 33 + k];
            sa[0][0] = fmaf(a0, vv.x, sa[0][0]); sa[0][1] = fmaf(a0, vv.y, sa[0][1]);
            sa[0][2] = fmaf(a0, vv.z, sa[0][2]); sa[0][3] = fmaf(a0, vv.w, sa[0][3]);
            sa[1][0] = fmaf(a1, vv.x, sa[1][0]); sa[1][1] = fmaf(a1, vv.y, sa[1][1]);
            sa[1][2] = fmaf(a1, vv.z, sa[1][2]); sa[1][3] = fmaf(a1, vv.w, sa[1][3]);
            sa[2][0] = fmaf(a2, vv.x, sa[2][0]); sa[2][1] = fmaf(a2, vv.y, sa[2][1]);
            sa[2][2] = fmaf(a2, vv.z, sa[2][2]); sa[2][3] = fmaf(a2, vv.w, sa[2][3]);
            sa[3][0] = fmaf(a3, vv.x, sa[3][0]); sa[3][1] = fmaf(a3, vv.y, sa[3][1]);
            sa[3][2] = fmaf(a3, vv.z, sa[3][2]); sa[3][3] = fmaf(a3, vv.w, sa[3][3]);
        }
#pragma unroll
        for (int i = 0; i < 4; i++)
            st4(sm + OQ + (r0 + i) * 128 + c0, sa[i][0], sa[i][1], sa[i][2], sa[i][3]);
    }
    __syncthreads();

    // ---------------- Phase 7: out_f = spatial @ Theta^T, residual ----------------
    gemm32(sm + OQ, &g_WT[3][0][0], sm + OWU, tid, acc);
#pragma unroll
    for (int i = 0; i < 4; i++) {
        float y0 = acc[i][0] + sm[OZ + (r0 + i) * 128 + c0 + 0];
        float y1 = acc[i][1] + sm[OZ + (r0 + i) * 128 + c0 + 1];
        float y2 = acc[i][2] + sm[OZ + (r0 + i) * 128 + c0 + 2];
        float y3 = acc[i][3] + sm[OZ + (r0 + i) * 128 + c0 + 3];
        st4(sm + OKK + (r0 + i) * 132 + c0, y0, y1, y2, y3);
    }
    __syncthreads();

    // ---------------- Phase 8: LayerNorm + masked store ----------------
    {
        float4 gv = ld4(sm + OGAM + lane * 4);
        float4 bv = ld4(sm + OBET + lane * 4);
#pragma unroll
        for (int q = 0; q < 4; q++) {
            int n = r0 + q;
            float4 y = ld4(sm + OKK + n * 132 + lane * 4);
            float s  = y.x + y.y + y.z + y.w;
            float s2 = y.x * y.x + y.y * y.y + y.z * y.z + y.w * y.w;
#pragma unroll
            for (int off = 16; off > 0; off >>= 1) {
                s  += __shfl_xor_sync(0xffffffffu, s, off);
                s2 += __shfl_xor_sync(0xffffffffu, s2, off);
            }
            float mu   = s * (1.f / 128.f);
            float var  = s2 * (1.f / 128.f) - mu * mu;
            float rstd = rsqrtf(var + 1e-5f);
            float4 o;
            o.x = (y.x - mu) * rstd * gv.x + bv.x;
            o.y = (y.y - mu) * rstd * gv.y + bv.y;
            o.z = (y.z - mu) * rstd * gv.z + bv.z;
            o.w = (y.w - mu) * rstd * gv.w + bv.w;
            if (sm[OMSK + n] != 0.f) o = make_float4(0.f, 0.f, 0.f, 0.f);
            reinterpret_cast<float4*>(out)[(((size_t)b * 32 + n) * 64 + t) * 32 + lane] = o;
        }
    }
}

extern "C" void kernel_launch(void* const* d_in, const int* in_sizes, int n_in,
                              void* d_out, int out_size) {
    (void)in_sizes; (void)n_in; (void)out_size;
    const float* x      = (const float*)d_in[0];
    const float* edge   = (const float*)d_in[1];
    const float* Aprior = (const float*)d_in[2];
    const unsigned char* pmask = (const unsigned char*)d_in[3];
    const float* Wq     = (const float*)d_in[4];
    const float* Wk     = (const float*)d_in[5];
    const float* Wv     = (const float*)d_in[6];
    const float* Th     = (const float*)d_in[7];
    const float* Wfuse  = (const float*)d_in[8];
    const float* W1     = (const float*)d_in[9];
    const float* b1     = (const float*)d_in[10];
    const float* W2     = (const float*)d_in[11];
    const float* b2     = (const float*)d_in[12];
    const float* gamma  = (const float*)d_in[13];
    const float* beta   = (const float*)d_in[14];
    const float* physw  = (const float*)d_in[15];
    const float* priorw = (const float*)d_in[16];
    float* out = (float*)d_out;

    transpose_weights_k<<<4, 256>>>(Wq, Wk, Wv, Th);

    cudaFuncSetAttribute(fused_gnn_kernel,
                         cudaFuncAttributeMaxDynamicSharedMemorySize, SMEMF * 4);
    fused_gnn_kernel<<<512, TPB, SMEMF * 4>>>(x, edge, Aprior, pmask, Wfuse, W1, b1, W2, b2,
                                              gamma, beta, physw, priorw, out);
}

// round 2
// speedup vs baseline: 2.0269x; 2.0269x over previous
#include <cuda_runtime.h>
#include <math.h>

#define TPB 256

// Prologue-computed operands (k-major: [k][out])
__device__ float g_P [128*128];  // (Wq^T Wk)[k][d] * (1/sqrt(128))
__device__ float g_Wv[128*128];  // Wv[d][k] transposed -> [k][d]
__device__ float g_Th[128*128];  // Theta transposed -> [k][d]
__device__ float g_U [128*64];   // [k][j]: j<32: (W1q@Wq)[j,k], j>=32: (W1k@Wk)[j-32,k]

__device__ __forceinline__ float4 ld4(const float* p){ return *reinterpret_cast<const float4*>(p); }
__device__ __forceinline__ void st4(float* p, float4 v){ *reinterpret_cast<float4*>(p) = v; }

__global__ void prep_kernel(const float* __restrict__ Wq, const float* __restrict__ Wk,
                            const float* __restrict__ Wv, const float* __restrict__ Th,
                            const float* __restrict__ W1)
{
    const int bx = blockIdx.x, tid = threadIdx.x;
    if (bx < 128) {
        // P[k][d] = sum_j Wq[j,k] * Wk[j,d], scaled
        const int k = bx, d = tid;
        float acc = 0.f;
#pragma unroll 4
        for (int j = 0; j < 128; j++) acc = fmaf(Wq[j*128+k], Wk[j*128+d], acc);
        g_P[k*128+d] = acc * 0.08838834764831845f;
    } else if (bx < 160) {
        // gU[k][j]
        const int bb = bx - 128;
        const int k  = bb*4 + (tid>>5);
        const int j0 = (tid & 31) * 2;
#pragma unroll
        for (int jj = 0; jj < 2; jj++) {
            const int j = j0 + jj;
            const float* w1row = (j < 32) ? (W1 + j*260) : (W1 + (j-32)*260 + 128);
            const float* wc    = (j < 32) ? Wq : Wk;
            float acc = 0.f;
#pragma unroll 4
            for (int d = 0; d < 128; d++) acc = fmaf(w1row[d], wc[d*128+k], acc);
            g_U[k*64 + j] = acc;
        }
    } else {
        // transposes of Wv / Theta
        const int i = bx - 160;              // 0..7
        const float* src = (i < 4) ? Wv : Th;
        float*       dst = (i < 4) ? g_Wv : g_Th;
        const int q = i & 3;
        for (int it = 0; it < 32; it++) {
            int idx = q*4096 + it*128 + tid;
            int d = idx >> 7, k = idx & 127;
            dst[k*128 + d] = src[idx];
        }
    }
}

// -------- shared memory layout (float offsets) --------
#define OZ     0        // Z   [32][128]
#define OZT    4096     // Z^T [128][33]
#define OC     8320     // C1 / spatial [32][128]
#define OV     12416    // V   [32][128]
#define OW     16512    // weight tiles 2x[32][128] / full gU [128][64]
#define OHQ    24704    // hq  [32][36]
#define OHKT   25856    // hk^T [32(j)][33]
#define OLOG   26912    // logits/alpha [32][36]
#define OB1    28064    // 32
#define OW2    28096    // 32
#define OWE    28128    // W1e [32][4]
#define OWF    28256    // 8 (W_fuse padded)
#define OGAM   28264    // 128
#define OBET   28392    // 128
#define OMSK   28520    // 32
#define OSC    28552    // [0]=phys_weight [1]=prior_weight [2]=b2
#define SMEMF  28556    // 114224 bytes

// out[32x128] = sIn[32x128(inStride)] @ gW[k=128][128], 8x4 tiles, 2-way split-K.
// grp1 stores partial into `partial`; grp0 adds its half (+optional residual) -> finalDst.
__device__ __forceinline__ void gemm256(const float* __restrict__ sIn, int inStride,
                                        const float* __restrict__ gW, float* sW,
                                        float* partial, float* finalDst,
                                        const float* resid, int tid)
{
    const int warp = tid >> 5, lane = tid & 31;
    const int grp = warp >> 2, wg = warp & 3;
    const int r0 = wg * 8, c0 = lane * 4;
    const int kbase = grp * 64;
    const int gt = wg * 32 + lane;
    float* sWg = sW + grp * 4096;

    float acc[8][4];
#pragma unroll
    for (int i = 0; i < 8; i++) { acc[i][0]=0.f; acc[i][1]=0.f; acc[i][2]=0.f; acc[i][3]=0.f; }

    for (int kt = 0; kt < 2; kt++) {
        __syncthreads();
        {   // stage 32x128 weight rows for this group
            const float4* src = reinterpret_cast<const float4*>(gW + (kbase + kt*32) * 128);
            float4* dw = reinterpret_cast<float4*>(sWg);
#pragma unroll
            for (int it = 0; it < 8; it++) dw[gt + it*128] = src[gt + it*128];
        }
        __syncthreads();
        const float* zc = sIn + kbase + kt*32;
#pragma unroll
        for (int kk = 0; kk < 32; kk += 4) {
            float4 z[8];
#pragma unroll
            for (int i = 0; i < 8; i++) z[i] = ld4(zc + (r0+i)*inStride + kk);
#pragma unroll
            for (int u = 0; u < 4; u++) {
                float4 wv = ld4(sWg + (kk+u)*128 + c0);
#pragma unroll
                for (int i = 0; i < 8; i++) {
                    float a = (u==0) ? z[i].x : (u==1) ? z[i].y : (u==2) ? z[i].z : z[i].w;
                    acc[i][0] = fmaf(a, wv.x, acc[i][0]);
                    acc[i][1] = fmaf(a, wv.y, acc[i][1]);
                    acc[i][2] = fmaf(a, wv.z, acc[i][2]);
                    acc[i][3] = fmaf(a, wv.w, acc[i][3]);
                }
            }
        }
    }
    __syncthreads();
    if (grp == 1) {
#pragma unroll
        for (int i = 0; i < 8; i++)
            st4(partial + (r0+i)*128 + c0, make_float4(acc[i][0], acc[i][1], acc[i][2], acc[i][3]));
    }
    __syncthreads();
    if (grp == 0) {
#pragma unroll
        for (int i = 0; i < 8; i++) {
            float4 p = ld4(partial + (r0+i)*128 + c0);
            float4 o = make_float4(acc[i][0]+p.x, acc[i][1]+p.y, acc[i][2]+p.z, acc[i][3]+p.w);
            if (resid) {
                float4 r = ld4(resid + (r0+i)*128 + c0);
                o.x += r.x; o.y += r.y; o.z += r.z; o.w += r.w;
            }
            st4(finalDst + (r0+i)*128 + c0, o);
        }
    }
    __syncthreads();
}

__global__ __launch_bounds__(TPB, 2)
void fused_gnn_kernel(const float* __restrict__ x, const float* __restrict__ edge,
                      const float* __restrict__ Aprior, const unsigned char* __restrict__ pmask,
                      const float* __restrict__ Wfuse, const float* __restrict__ W1,
                      const float* __restrict__ b1g, const float* __restrict__ W2g,
                      const float* __restrict__ b2g, const float* __restrict__ gammag,
                      const float* __restrict__ betag, const float* __restrict__ physw,
                      const float* __restrict__ priorw, float* __restrict__ out)
{
    extern __shared__ float sm[];
    const int tid = threadIdx.x;
    const int bt = blockIdx.x;
    const int b = bt >> 6, t = bt & 63;
    const int warp = tid >> 5, lane = tid & 31;

    // ---------------- Phase 0: stage Z (+ Z^T) and small tensors ----------------
#pragma unroll
    for (int it = 0; it < 4; it++) {
        int idx = tid + it * TPB;              // idx = n*32 + dgroup
        int n = idx >> 5, dg = idx & 31;
        float4 v = ld4(x + ((((size_t)b*32 + n)*64 + t)*128) + dg*4);
        st4(sm + OZ + n*128 + dg*4, v);
        sm[OZT + (dg*4+0)*33 + n] = v.x;
        sm[OZT + (dg*4+1)*33 + n] = v.y;
        sm[OZT + (dg*4+2)*33 + n] = v.z;
        sm[OZT + (dg*4+3)*33 + n] = v.w;
    }
    if (tid < 32) {
        sm[OB1 + tid]  = b1g[tid];
        sm[OW2 + tid]  = W2g[tid];
        sm[OMSK + tid] = pmask[b*32 + tid] ? 1.f : 0.f;
    } else if (tid < 40) {
        int i = tid - 32;
        sm[OWF + i] = (i < 5) ? Wfuse[i] : 0.f;
    } else if (tid == 40) sm[OSC + 0] = physw[0];
    else if (tid == 41)   sm[OSC + 1] = priorw[0];
    else if (tid == 42)   sm[OSC + 2] = b2g[0];
    if (tid >= 64 && tid < 192) {   // W1e [j][e]
        int i = tid - 64;
        sm[OWE + i] = W1[(i>>2)*260 + 256 + (i&3)];
    }
    if (tid >= 128) {
        sm[OGAM + tid-128] = gammag[tid-128];
        sm[OBET + tid-128] = betag[tid-128];
    }
    __syncthreads();

    // ---------------- Phase 1: C1 = Z @ P ----------------
    gemm256(sm + OZ, 128, g_P, sm + OW, sm + OC, sm + OC, nullptr, tid);

    // ---------------- Phase 2: content = C1 @ Z^T -> sLOG ----------------
    {
        float acc4[4] = {0.f, 0.f, 0.f, 0.f};
        for (int k = 0; k < 128; k += 4) {
            float zt0 = sm[OZT + (k+0)*33 + lane];
            float zt1 = sm[OZT + (k+1)*33 + lane];
            float zt2 = sm[OZT + (k+2)*33 + lane];
            float zt3 = sm[OZT + (k+3)*33 + lane];
#pragma unroll
            for (int i = 0; i < 4; i++) {
                float4 c = ld4(sm + OC + (warp*4+i)*128 + k);
                acc4[i] = fmaf(c.x, zt0, acc4[i]);
                acc4[i] = fmaf(c.y, zt1, acc4[i]);
                acc4[i] = fmaf(c.z, zt2, acc4[i]);
                acc4[i] = fmaf(c.w, zt3, acc4[i]);
            }
        }
#pragma unroll
        for (int i = 0; i < 4; i++) sm[OLOG + (warp*4+i)*36 + lane] = acc4[i];
    }

    // ---------------- Phase 3: V = Z @ Wv^T ----------------
    gemm256(sm + OZ, 128, g_Wv, sm + OW, sm + OV, sm + OV, nullptr, tid);

    // ---------------- Prefetch edge / prior (consumed in phys phase) ----------------
    const int pn = tid >> 3, pm0 = (tid & 7) << 2;
    float4 e4[4]; float lpr[4];
    {
        const float wf0 = sm[OWF+0], wf1 = sm[OWF+1], wf2 = sm[OWF+2],
                    wf3 = sm[OWF+3], wf4 = sm[OWF+4];
#pragma unroll
        for (int mm = 0; mm < 4; mm++) {
            size_t pair = (size_t)bt*1024 + pn*32 + pm0 + mm;
            e4[mm] = ld4(edge + pair*4);
            const float* ap = Aprior + pair*5;
            float p = ap[0]*wf0 + ap[1]*wf1 + ap[2]*wf2 + ap[3]*wf3 + ap[4]*wf4;
            if (!isfinite(p)) p = 0.f;
            p = fmaxf(p, 0.f);
            lpr[mm] = logf(p + 1e-6f);
        }
    }

    // ---------------- Phase 4: H = Z @ gU  (hq | hk), split-K ----------------
    {
        // stage full gU [128][64] into OW
        {
            const float4* src = reinterpret_cast<const float4*>(g_U);
            float4* dw = reinterpret_cast<float4*>(sm + OW);
#pragma unroll
            for (int it = 0; it < 8; it++) dw[tid + it*TPB] = src[tid + it*TPB];
        }
        __syncthreads();

        const int grp = warp >> 2, wg = warp & 3;
        const int r0 = wg*8 + (lane>>4)*4;
        const int c0 = (lane & 15) * 4;
        const int kb = grp * 64;
        float acc[4][4];
#pragma unroll
        for (int i = 0; i < 4; i++) { acc[i][0]=0.f; acc[i][1]=0.f; acc[i][2]=0.f; acc[i][3]=0.f; }

        const float* sU = sm + OW;
        for (int k = kb; k < kb + 64; k += 4) {
            float4 z[4];
#pragma unroll
            for (int i = 0; i < 4; i++) z[i] = ld4(sm + OZ + (r0+i)*128 + k);
#pragma unroll
            for (int u = 0; u < 4; u++) {
                float4 uv = ld4(sU + (k+u)*64 + c0);
#pragma unroll
                for (int i = 0; i < 4; i++) {
                    float a = (u==0) ? z[i].x : (u==1) ? z[i].y : (u==2) ? z[i].z : z[i].w;
                    acc[i][0] = fmaf(a, uv.x, acc[i][0]);
                    acc[i][1] = fmaf(a, uv.y, acc[i][1]);
                    acc[i][2] = fmaf(a, uv.z, acc[i][2]);
                    acc[i][3] = fmaf(a, uv.w, acc[i][3]);
                }
            }
        }
        __syncthreads();
        float* scr = sm + OZT;    // ZT is dead after Phase 2 -> reduction scratch
        if (grp == 1) {
#pragma unroll
            for (int i = 0; i < 4; i++)
                st4(scr + (r0+i)*64 + c0, make_float4(acc[i][0], acc[i][1], acc[i][2], acc[i][3]));
        }
        __syncthreads();
        if (grp == 0) {
#pragma unroll
            for (int i = 0; i < 4; i++) {
                float4 p = ld4(scr + (r0+i)*64 + c0);
                float h0 = acc[i][0]+p.x, h1 = acc[i][1]+p.y, h2 = acc[i][2]+p.z, h3 = acc[i][3]+p.w;
                int n = r0 + i;
                if (c0 < 32) {
                    sm[OHQ + n*36 + c0+0] = h0; sm[OHQ + n*36 + c0+1] = h1;
                    sm[OHQ + n*36 + c0+2] = h2; sm[OHQ + n*36 + c0+3] = h3;
                } else {
                    int j = c0 - 32;
                    sm[OHKT + (j+0)*33 + n] = h0; sm[OHKT + (j+1)*33 + n] = h1;
                    sm[OHKT + (j+2)*33 + n] = h2; sm[OHKT + (j+3)*33 + n] = h3;
                }
            }
        }
        __syncthreads();
    }

    // ---------------- Phase 5: phys MLP + prior + logits ----------------
    {
        float ph[4] = {0.f, 0.f, 0.f, 0.f};
#pragma unroll
        for (int j = 0; j < 32; j += 4) {
            float4 hqv = ld4(sm + OHQ + pn*36 + j);
            float4 b1v = ld4(sm + OB1 + j);
            float4 w2v = ld4(sm + OW2 + j);
            float hq4[4] = {hqv.x, hqv.y, hqv.z, hqv.w};
            float b14[4] = {b1v.x, b1v.y, b1v.z, b1v.w};
            float w24[4] = {w2v.x, w2v.y, w2v.z, w2v.w};
#pragma unroll
            for (int jj = 0; jj < 4; jj++) {
                int jc = j + jj;
                float hqb = hq4[jj] + b14[jj];
                float w2s = w24[jj];
                float4 we = ld4(sm + OWE + jc*4);
#pragma unroll
                for (int mm = 0; mm < 4; mm++) {
                    float h = hqb + sm[OHKT + jc*33 + pm0 + mm]
                            + e4[mm].x*we.x + e4[mm].y*we.y
                            + e4[mm].z*we.z + e4[mm].w*we.w;
                    h = fmaxf(h, 0.f);
                    ph[mm] = fmaf(h, w2s, ph[mm]);
                }
            }
        }
        float pw = sm[OSC+0], prw = sm[OSC+1], b2v = sm[OSC+2];
        float mn = sm[OMSK + pn];
#pragma unroll
        for (int mm = 0; mm < 4; mm++) {
            float lg = sm[OLOG + pn*36 + pm0 + mm]      // content (pre-scaled)
                     + pw * (ph[mm] + b2v)
                     + prw * lpr[mm];
            if (mn != 0.f || sm[OMSK + pm0 + mm] != 0.f) lg = -1e9f;
            sm[OLOG + pn*36 + pm0 + mm] = lg;
        }
    }
    __syncthreads();

    // ---------------- Phase 6: softmax (warp per 4 rows) ----------------
#pragma unroll
    for (int q = 0; q < 4; q++) {
        int n = warp*4 + q;
        float v = sm[OLOG + n*36 + lane];
        float mx = v;
#pragma unroll
        for (int off = 16; off > 0; off >>= 1)
            mx = fmaxf(mx, __shfl_xor_sync(0xffffffffu, mx, off));
        float e = expf(v - mx);
        float s = e;
#pragma unroll
        for (int off = 16; off > 0; off >>= 1)
            s += __shfl_xor_sync(0xffffffffu, s, off);
        sm[OLOG + n*36 + lane] = e / s;
    }
    __syncthreads();

    // ---------------- Phase 7: spatial = alpha @ V -> sC (split-K over 32) ----------------
    {
        const int grp = warp >> 2, wg = warp & 3;
        const int r0 = wg * 8, c0 = lane * 4;
        const int kb = grp * 16;
        float acc[8][4];
#pragma unroll
        for (int i = 0; i < 8; i++) { acc[i][0]=0.f; acc[i][1]=0.f; acc[i][2]=0.f; acc[i][3]=0.f; }
#pragma unroll
        for (int kk = 0; kk < 16; kk += 4) {
            float4 a[8];
#pragma unroll
            for (int i = 0; i < 8; i++) a[i] = ld4(sm + OLOG + (r0+i)*36 + kb + kk);
#pragma unroll
            for (int u = 0; u < 4; u++) {
                float4 vv = ld4(sm + OV + (kb+kk+u)*128 + c0);
#pragma unroll
                for (int i = 0; i < 8; i++) {
                    float av = (u==0) ? a[i].x : (u==1) ? a[i].y : (u==2) ? a[i].z : a[i].w;
                    acc[i][0] = fmaf(av, vv.x, acc[i][0]);
                    acc[i][1] = fmaf(av, vv.y, acc[i][1]);
                    acc[i][2] = fmaf(av, vv.z, acc[i][2]);
                    acc[i][3] = fmaf(av, vv.w, acc[i][3]);
                }
            }
        }
        __syncthreads();
        if (grp == 1) {
#pragma unroll
            for (int i = 0; i < 8; i++)
                st4(sm + OC + (r0+i)*128 + c0, make_float4(acc[i][0], acc[i][1], acc[i][2], acc[i][3]));
        }
        __syncthreads();
        if (grp == 0) {
#pragma unroll
            for (int i = 0; i < 8; i++) {
                float4 p = ld4(sm + OC + (r0+i)*128 + c0);
                st4(sm + OC + (r0+i)*128 + c0,
                    make_float4(acc[i][0]+p.x, acc[i][1]+p.y, acc[i][2]+p.z, acc[i][3]+p.w));
            }
        }
        __syncthreads();
    }

    // ---------------- Phase 8: y = Z + spatial @ Theta^T  (into sZ) ----------------
    gemm256(sm + OC, 128, g_Th, sm + OW, sm + OV /*partial*/, sm + OZ /*final*/, sm + OZ /*residual*/, tid);

    // ---------------- Phase 9: LayerNorm + masked store ----------------
    {
        float4 gv = ld4(sm + OGAM + lane*4);
        float4 bv = ld4(sm + OBET + lane*4);
#pragma unroll
        for (int q = 0; q < 4; q++) {
            int n = warp*4 + q;
            float4 y = ld4(sm + OZ + n*128 + lane*4);
            float s  = y.x + y.y + y.z + y.w;
            float s2 = y.x*y.x + y.y*y.y + y.z*y.z + y.w*y.w;
#pragma unroll
            for (int off = 16; off > 0; off >>= 1) {
                s  += __shfl_xor_sync(0xffffffffu, s, off);
                s2 += __shfl_xor_sync(0xffffffffu, s2, off);
            }
            float mu   = s * (1.f/128.f);
            float var  = s2 * (1.f/128.f) - mu*mu;
            float rstd = rsqrtf(var + 1e-5f);
            float4 o;
            o.x = (y.x - mu)*rstd*gv.x + bv.x;
            o.y = (y.y - mu)*rstd*gv.y + bv.y;
            o.z = (y.z - mu)*rstd*gv.z + bv.z;
            o.w = (y.w - mu)*rstd*gv.w + bv.w;
            if (sm[OMSK + n] != 0.f) o = make_float4(0.f, 0.f, 0.f, 0.f);
            reinterpret_cast<float4*>(out)[(((size_t)b*32 + n)*64 + t)*32 + lane] = o;
        }
    }
}

extern "C" void kernel_launch(void* const* d_in, const int* in_sizes, int n_in,
                              void* d_out, int out_size) {
    (void)in_sizes; (void)n_in; (void)out_size;
    const float* x      = (const float*)d_in[0];
    const float* edge   = (const float*)d_in[1];
    const float* Aprior = (const float*)d_in[2];
    const unsigned char* pmask = (const unsigned char*)d_in[3];
    const float* Wq     = (const float*)d_in[4];
    const float* Wk     = (const float*)d_in[5];
    const float* Wv     = (const float*)d_in[6];
    const float* Th     = (const float*)d_in[7];
    const float* Wfuse  = (const float*)d_in[8];
    const float* W1     = (const float*)d_in[9];
    const float* b1     = (const float*)d_in[10];
    const float* W2     = (const float*)d_in[11];
    const float* b2     = (const float*)d_in[12];
    const float* gamma  = (const float*)d_in[13];
    const float* beta   = (const float*)d_in[14];
    const float* physw  = (const float*)d_in[15];
    const float* priorw = (const float*)d_in[16];
    float* out = (float*)d_out;

    prep_kernel<<<168, 128>>>(Wq, Wk, Wv, Th, W1);

    cudaFuncSetAttribute(fused_gnn_kernel,
                         cudaFuncAttributeMaxDynamicSharedMemorySize, SMEMF * 4);
    fused_gnn_kernel<<<512, TPB, SMEMF * 4>>>(x, edge, Aprior, pmask, Wfuse, W1, b1, W2, b2,
                                              gamma, beta, physw, priorw, out);
}

// round 3
// speedup vs baseline: 2.1050x; 1.0385x over previous
#include <cuda_runtime.h>
#include <math.h>

#define TPB 256

// Prologue-computed operands (k-major: [k][out])
__device__ float g_P [128*128];  // (Wq^T Wk)[k][d] * (1/sqrt(128))
__device__ float g_Wv[128*128];  // Wv[d][k] transposed -> [k][d]
__device__ float g_Th[128*128];  // Theta transposed -> [k][d]
__device__ float g_U [128*64];   // [k][j]: j<32: (W1q@Wq)[j,k], j>=32: (W1k@Wk)[j-32,k]

typedef unsigned long long u64;

__device__ __forceinline__ float4 ld4(const float* p){ return *reinterpret_cast<const float4*>(p); }
__device__ __forceinline__ void st4(float* p, float4 v){ *reinterpret_cast<float4*>(p) = v; }
__device__ __forceinline__ ulonglong2 ldp2(const float* p){ return *reinterpret_cast<const ulonglong2*>(p); }
__device__ __forceinline__ void stp2(float* p, u64 a, u64 b){
    ulonglong2 v; v.x = a; v.y = b;
    *reinterpret_cast<ulonglong2*>(p) = v;
}
__device__ __forceinline__ u64 pk2(float x, float y){
    u64 r; asm("mov.b64 %0, {%1,%2};" : "=l"(r) : "f"(x), "f"(y)); return r;
}
__device__ __forceinline__ float2 upk2(u64 v){
    float2 f; asm("mov.b64 {%0,%1}, %2;" : "=f"(f.x), "=f"(f.y) : "l"(v)); return f;
}
__device__ __forceinline__ u64 fma2(u64 a, u64 b, u64 c){
    u64 d; asm("fma.rn.f32x2 %0, %1, %2, %3;" : "=l"(d) : "l"(a), "l"(b), "l"(c)); return d;
}
__device__ __forceinline__ u64 add2(u64 a, u64 b){
    u64 d; asm("add.rn.f32x2 %0, %1, %2;" : "=l"(d) : "l"(a), "l"(b)); return d;
}

__global__ void prep_kernel(const float* __restrict__ Wq, const float* __restrict__ Wk,
                            const float* __restrict__ Wv, const float* __restrict__ Th,
                            const float* __restrict__ W1)
{
    const int bx = blockIdx.x, tid = threadIdx.x;
    if (bx < 128) {
        const int k = bx, d = tid;
        float acc = 0.f;
#pragma unroll 4
        for (int j = 0; j < 128; j++) acc = fmaf(Wq[j*128+k], Wk[j*128+d], acc);
        g_P[k*128+d] = acc * 0.08838834764831845f;
    } else if (bx < 160) {
        const int bb = bx - 128;
        const int k  = bb*4 + (tid>>5);
        const int j0 = (tid & 31) * 2;
#pragma unroll
        for (int jj = 0; jj < 2; jj++) {
            const int j = j0 + jj;
            const float* w1row = (j < 32) ? (W1 + j*260) : (W1 + (j-32)*260 + 128);
            const float* wc    = (j < 32) ? Wq : Wk;
            float acc = 0.f;
#pragma unroll 4
            for (int d = 0; d < 128; d++) acc = fmaf(w1row[d], wc[d*128+k], acc);
            g_U[k*64 + j] = acc;
        }
    } else {
        const int i = bx - 160;              // 0..7
        const float* src = (i < 4) ? Wv : Th;
        float*       dst = (i < 4) ? g_Wv : g_Th;
        const int q = i & 3;
        for (int it = 0; it < 32; it++) {
            int idx = q*4096 + it*128 + tid;
            int d = idx >> 7, k = idx & 127;
            dst[k*128 + d] = src[idx];
        }
    }
}

// -------- shared memory layout (float offsets) --------
#define OZ     0        // Z   [32][128]
#define OZT    4096     // Z^T [128][33]
#define OC     8320     // C1 / spatial [32][128]
#define OV     12416    // V   [32][128]
#define OW     16512    // weight tiles 2x[32][128] / full gU [128][64]
#define OHQ    24704    // hq  [32][36]
#define OHKT   25856    // hk^T [32(j)][33]
#define OLOG   26912    // logits/alpha [32][36]
#define OB1    28064    // 32
#define OW2    28096    // 32
#define OWE    28128    // W1e [32][4]
#define OWF    28256    // 8 (W_fuse padded)
#define OGAM   28264    // 128
#define OBET   28392    // 128
#define OMSK   28520    // 32
#define OSC    28552    // [0]=phys_weight [1]=prior_weight [2]=b2
#define SMEMF  28556    // 114224 bytes

// out[32x128] = sIn[32x128] @ gW[k=128][128], 8x4 tiles (packed f32x2 cols), 2-way split-K.
__device__ __forceinline__ void gemm256(const float* __restrict__ sIn, int inStride,
                                        const float* __restrict__ gW, float* sW,
                                        float* partial, float* finalDst,
                                        const float* resid, int tid)
{
    const int warp = tid >> 5, lane = tid & 31;
    const int grp = warp >> 2, wg = warp & 3;
    const int r0 = wg * 8, c0 = lane * 4;
    const int kbase = grp * 64;
    const int gt = wg * 32 + lane;
    float* sWg = sW + grp * 4096;

    u64 acc[8][2];
#pragma unroll
    for (int i = 0; i < 8; i++) { acc[i][0] = 0ull; acc[i][1] = 0ull; }

    for (int kt = 0; kt < 2; kt++) {
        __syncthreads();
        {
            const float4* src = reinterpret_cast<const float4*>(gW + (kbase + kt*32) * 128);
            float4* dw = reinterpret_cast<float4*>(sWg);
#pragma unroll
            for (int it = 0; it < 8; it++) dw[gt + it*128] = src[gt + it*128];
        }
        __syncthreads();
        const float* zc = sIn + kbase + kt*32;
#pragma unroll
        for (int kk = 0; kk < 32; kk += 4) {
            float4 z[8];
#pragma unroll
            for (int i = 0; i < 8; i++) z[i] = ld4(zc + (r0+i)*inStride + kk);
#pragma unroll
            for (int u = 0; u < 4; u++) {
                ulonglong2 w2 = ldp2(sWg + (kk+u)*128 + c0);
#pragma unroll
                for (int i = 0; i < 8; i++) {
                    float a = (u==0) ? z[i].x : (u==1) ? z[i].y : (u==2) ? z[i].z : z[i].w;
                    u64 a2 = pk2(a, a);
                    acc[i][0] = fma2(a2, w2.x, acc[i][0]);
                    acc[i][1] = fma2(a2, w2.y, acc[i][1]);
                }
            }
        }
    }
    __syncthreads();
    if (grp == 1) {
#pragma unroll
        for (int i = 0; i < 8; i++)
            stp2(partial + (r0+i)*128 + c0, acc[i][0], acc[i][1]);
    }
    __syncthreads();
    if (grp == 0) {
#pragma unroll
        for (int i = 0; i < 8; i++) {
            ulonglong2 p = ldp2(partial + (r0+i)*128 + c0);
            u64 o0 = add2(acc[i][0], p.x);
            u64 o1 = add2(acc[i][1], p.y);
            if (resid) {
                ulonglong2 r = ldp2(resid + (r0+i)*128 + c0);
                o0 = add2(o0, r.x);
                o1 = add2(o1, r.y);
            }
            stp2(finalDst + (r0+i)*128 + c0, o0, o1);
        }
    }
    __syncthreads();
}

__global__ __launch_bounds__(TPB, 2)
void fused_gnn_kernel(const float* __restrict__ x, const float* __restrict__ edge,
                      const float* __restrict__ Aprior, const unsigned char* __restrict__ pmask,
                      const float* __restrict__ Wfuse, const float* __restrict__ W1,
                      const float* __restrict__ b1g, const float* __restrict__ W2g,
                      const float* __restrict__ b2g, const float* __restrict__ gammag,
                      const float* __restrict__ betag, const float* __restrict__ physw,
                      const float* __restrict__ priorw, float* __restrict__ out)
{
    extern __shared__ float sm[];
    const int tid = threadIdx.x;
    const int bt = blockIdx.x;
    const int b = bt >> 6, t = bt & 63;
    const int warp = tid >> 5, lane = tid & 31;

    // ---------------- Phase 0: stage Z (+ Z^T) and small tensors ----------------
#pragma unroll
    for (int it = 0; it < 4; it++) {
        int idx = tid + it * TPB;              // idx = n*32 + dgroup
        int n = idx >> 5, dg = idx & 31;
        float4 v = ld4(x + ((((size_t)b*32 + n)*64 + t)*128) + dg*4);
        st4(sm + OZ + n*128 + dg*4, v);
        sm[OZT + (dg*4+0)*33 + n] = v.x;
        sm[OZT + (dg*4+1)*33 + n] = v.y;
        sm[OZT + (dg*4+2)*33 + n] = v.z;
        sm[OZT + (dg*4+3)*33 + n] = v.w;
    }
    if (tid < 32) {
        sm[OB1 + tid]  = b1g[tid];
        sm[OW2 + tid]  = W2g[tid];
        sm[OMSK + tid] = pmask[b*32 + tid] ? 1.f : 0.f;
    } else if (tid < 40) {
        int i = tid - 32;
        sm[OWF + i] = (i < 5) ? Wfuse[i] : 0.f;
    } else if (tid == 40) sm[OSC + 0] = physw[0];
    else if (tid == 41)   sm[OSC + 1] = priorw[0];
    else if (tid == 42)   sm[OSC + 2] = b2g[0];
    if (tid >= 64 && tid < 192) {   // W1e [j][e]
        int i = tid - 64;
        sm[OWE + i] = W1[(i>>2)*260 + 256 + (i&3)];
    }
    if (tid >= 128) {
        sm[OGAM + tid-128] = gammag[tid-128];
        sm[OBET + tid-128] = betag[tid-128];
    }
    __syncthreads();

    // ---------------- Phase 1: C1 = Z @ P ----------------
    gemm256(sm + OZ, 128, g_P, sm + OW, sm + OC, sm + OC, nullptr, tid);

    // ---------------- Phase 2: content = C1 @ Z^T -> sLOG (packed over k-pairs) ----------------
    {
        u64 acc2[4] = {0ull, 0ull, 0ull, 0ull};
        for (int k = 0; k < 128; k += 4) {
            float zt0 = sm[OZT + (k+0)*33 + lane];
            float zt1 = sm[OZT + (k+1)*33 + lane];
            float zt2 = sm[OZT + (k+2)*33 + lane];
            float zt3 = sm[OZT + (k+3)*33 + lane];
            u64 zt01 = pk2(zt0, zt1);
            u64 zt23 = pk2(zt2, zt3);
#pragma unroll
            for (int i = 0; i < 4; i++) {
                ulonglong2 c2 = ldp2(sm + OC + (warp*4+i)*128 + k);
                acc2[i] = fma2(c2.x, zt01, acc2[i]);
                acc2[i] = fma2(c2.y, zt23, acc2[i]);
            }
        }
#pragma unroll
        for (int i = 0; i < 4; i++) {
            float2 f = upk2(acc2[i]);
            sm[OLOG + (warp*4+i)*36 + lane] = f.x + f.y;
        }
    }

    // ---------------- Phase 3: V = Z @ Wv^T ----------------
    gemm256(sm + OZ, 128, g_Wv, sm + OW, sm + OV, sm + OV, nullptr, tid);

    // ---------------- Prefetch edge / prior ----------------
    const int pn = tid >> 3, pm0 = (tid & 7) << 2;
    float4 e4[4]; float lpr[4];
    {
        const float wf0 = sm[OWF+0], wf1 = sm[OWF+1], wf2 = sm[OWF+2],
                    wf3 = sm[OWF+3], wf4 = sm[OWF+4];
#pragma unroll
        for (int mm = 0; mm < 4; mm++) {
            size_t pair = (size_t)bt*1024 + pn*32 + pm0 + mm;
            e4[mm] = ld4(edge + pair*4);
            const float* ap = Aprior + pair*5;
            float p = ap[0]*wf0 + ap[1]*wf1 + ap[2]*wf2 + ap[3]*wf3 + ap[4]*wf4;
            if (!isfinite(p)) p = 0.f;
            p = fmaxf(p, 0.f);
            lpr[mm] = logf(p + 1e-6f);
        }
    }

    // ---------------- Phase 4: H = Z @ gU  (hq | hk), split-K, packed ----------------
    {
        {
            const float4* src = reinterpret_cast<const float4*>(g_U);
            float4* dw = reinterpret_cast<float4*>(sm + OW);
#pragma unroll
            for (int it = 0; it < 8; it++) dw[tid + it*TPB] = src[tid + it*TPB];
        }
        __syncthreads();

        const int grp = warp >> 2, wg = warp & 3;
        const int r0 = wg*8 + (lane>>4)*4;
        const int c0 = (lane & 15) * 4;
        const int kb = grp * 64;
        u64 acc[4][2];
#pragma unroll
        for (int i = 0; i < 4; i++) { acc[i][0] = 0ull; acc[i][1] = 0ull; }

        const float* sU = sm + OW;
        for (int k = kb; k < kb + 64; k += 4) {
            float4 z[4];
#pragma unroll
            for (int i = 0; i < 4; i++) z[i] = ld4(sm + OZ + (r0+i)*128 + k);
#pragma unroll
            for (int u = 0; u < 4; u++) {
                ulonglong2 u2 = ldp2(sU + (k+u)*64 + c0);
#pragma unroll
                for (int i = 0; i < 4; i++) {
                    float a = (u==0) ? z[i].x : (u==1) ? z[i].y : (u==2) ? z[i].z : z[i].w;
                    u64 a2 = pk2(a, a);
                    acc[i][0] = fma2(a2, u2.x, acc[i][0]);
                    acc[i][1] = fma2(a2, u2.y, acc[i][1]);
                }
            }
        }
        __syncthreads();
        float* scr = sm + OZT;    // ZT is dead -> reduction scratch
        if (grp == 1) {
#pragma unroll
            for (int i = 0; i < 4; i++)
                stp2(scr + (r0+i)*64 + c0, acc[i][0], acc[i][1]);
        }
        __syncthreads();
        if (grp == 0) {
#pragma unroll
            for (int i = 0; i < 4; i++) {
                ulonglong2 p = ldp2(scr + (r0+i)*64 + c0);
                float2 hA = upk2(add2(acc[i][0], p.x));
                float2 hB = upk2(add2(acc[i][1], p.y));
                int n = r0 + i;
                if (c0 < 32) {
                    sm[OHQ + n*36 + c0+0] = hA.x; sm[OHQ + n*36 + c0+1] = hA.y;
                    sm[OHQ + n*36 + c0+2] = hB.x; sm[OHQ + n*36 + c0+3] = hB.y;
                } else {
                    int j = c0 - 32;
                    sm[OHKT + (j+0)*33 + n] = hA.x; sm[OHKT + (j+1)*33 + n] = hA.y;
                    sm[OHKT + (j+2)*33 + n] = hB.x; sm[OHKT + (j+3)*33 + n] = hB.y;
                }
            }
        }
        __syncthreads();
    }

    // ---------------- Phase 5: phys MLP + prior + logits ----------------
    {
        float ph[4] = {0.f, 0.f, 0.f, 0.f};
#pragma unroll
        for (int j = 0; j < 32; j += 4) {
            float4 hqv = ld4(sm + OHQ + pn*36 + j);
            float4 b1v = ld4(sm + OB1 + j);
            float4 w2v = ld4(sm + OW2 + j);
            float hq4[4] = {hqv.x, hqv.y, hqv.z, hqv.w};
            float b14[4] = {b1v.x, b1v.y, b1v.z, b1v.w};
            float w24[4] = {w2v.x, w2v.y, w2v.z, w2v.w};
#pragma unroll
            for (int jj = 0; jj < 4; jj++) {
                int jc = j + jj;
                float hqb = hq4[jj] + b14[jj];
                float w2s = w24[jj];
                float4 we = ld4(sm + OWE + jc*4);
#pragma unroll
                for (int mm = 0; mm < 4; mm++) {
                    float h = hqb + sm[OHKT + jc*33 + pm0 + mm]
                            + e4[mm].x*we.x + e4[mm].y*we.y
                            + e4[mm].z*we.z + e4[mm].w*we.w;
                    h = fmaxf(h, 0.f);
                    ph[mm] = fmaf(h, w2s, ph[mm]);
                }
            }
        }
        float pw = sm[OSC+0], prw = sm[OSC+1], b2v = sm[OSC+2];
        float mn = sm[OMSK + pn];
#pragma unroll
        for (int mm = 0; mm < 4; mm++) {
            float lg = sm[OLOG + pn*36 + pm0 + mm]
                     + pw * (ph[mm] + b2v)
                     + prw * lpr[mm];
            if (mn != 0.f || sm[OMSK + pm0 + mm] != 0.f) lg = -1e9f;
            sm[OLOG + pn*36 + pm0 + mm] = lg;
        }
    }
    __syncthreads();

    // ---------------- Phase 6: softmax (warp per 4 rows) ----------------
#pragma unroll
    for (int q = 0; q < 4; q++) {
        int n = warp*4 + q;
        float v = sm[OLOG + n*36 + lane];
        float mx = v;
#pragma unroll
        for (int off = 16; off > 0; off >>= 1)
            mx = fmaxf(mx, __shfl_xor_sync(0xffffffffu, mx, off));
        float e = expf(v - mx);
        float s = e;
#pragma unroll
        for (int off = 16; off > 0; off >>= 1)
            s += __shfl_xor_sync(0xffffffffu, s, off);
        sm[OLOG + n*36 + lane] = e / s;
    }
    __syncthreads();

    // ---------------- Phase 7: spatial = alpha @ V -> sC (split-K, packed) ----------------
    {
        const int grp = warp >> 2, wg = warp & 3;
        const int r0 = wg * 8, c0 = lane * 4;
        const int kb = grp * 16;
        u64 acc[8][2];
#pragma unroll
        for (int i = 0; i < 8; i++) { acc[i][0] = 0ull; acc[i][1] = 0ull; }
#pragma unroll
        for (int kk = 0; kk < 16; kk += 4) {
            float4 a[8];
#pragma unroll
            for (int i = 0; i < 8; i++) a[i] = ld4(sm + OLOG + (r0+i)*36 + kb + kk);
#pragma unroll
            for (int u = 0; u < 4; u++) {
                ulonglong2 v2 = ldp2(sm + OV + (kb+kk+u)*128 + c0);
#pragma unroll
                for (int i = 0; i < 8; i++) {
                    float av = (u==0) ? a[i].x : (u==1) ? a[i].y : (u==2) ? a[i].z : a[i].w;
                    u64 a2 = pk2(av, av);
                    acc[i][0] = fma2(a2, v2.x, acc[i][0]);
                    acc[i][1] = fma2(a2, v2.y, acc[i][1]);
                }
            }
        }
        __syncthreads();
        if (grp == 1) {
#pragma unroll
            for (int i = 0; i < 8; i++)
                stp2(sm + OC + (r0+i)*128 + c0, acc[i][0], acc[i][1]);
        }
        __syncthreads();
        if (grp == 0) {
#pragma unroll
            for (int i = 0; i < 8; i++) {
                ulonglong2 p = ldp2(sm + OC + (r0+i)*128 + c0);
                stp2(sm + OC + (r0+i)*128 + c0,
                     add2(acc[i][0], p.x), add2(acc[i][1], p.y));
            }
        }
        __syncthreads();
    }

    // ---------------- Phase 8: y = Z + spatial @ Theta^T  (into sZ) ----------------
    gemm256(sm + OC, 128, g_Th, sm + OW, sm + OV /*partial*/, sm + OZ /*final*/, sm + OZ /*residual*/, tid);

    // ---------------- Phase 9: LayerNorm + masked store ----------------
    {
        float4 gv = ld4(sm + OGAM + lane*4);
        float4 bv = ld4(sm + OBET + lane*4);
#pragma unroll
        for (int q = 0; q < 4; q++) {
            int n = warp*4 + q;
            float4 y = ld4(sm + OZ + n*128 + lane*4);
            float s  = y.x + y.y + y.z + y.w;
            float s2 = y.x*y.x + y.y*y.y + y.z*y.z + y.w*y.w;
#pragma unroll
            for (int off = 16; off > 0; off >>= 1) {
                s  += __shfl_xor_sync(0xffffffffu, s, off);
                s2 += __shfl_xor_sync(0xffffffffu, s2, off);
            }
            float mu   = s * (1.f/128.f);
            float var  = s2 * (1.f/128.f) - mu*mu;
            float rstd = rsqrtf(var + 1e-5f);
            float4 o;
            o.x = (y.x - mu)*rstd*gv.x + bv.x;
            o.y = (y.y - mu)*rstd*gv.y + bv.y;
            o.z = (y.z - mu)*rstd*gv.z + bv.z;
            o.w = (y.w - mu)*rstd*gv.w + bv.w;
            if (sm[OMSK + n] != 0.f) o = make_float4(0.f, 0.f, 0.f, 0.f);
            reinterpret_cast<float4*>(out)[(((size_t)b*32 + n)*64 + t)*32 + lane] = o;
        }
    }
}

extern "C" void kernel_launch(void* const* d_in, const int* in_sizes, int n_in,
                              void* d_out, int out_size) {
    (void)in_sizes; (void)n_in; (void)out_size;
    const float* x      = (const float*)d_in[0];
    const float* edge   = (const float*)d_in[1];
    const float* Aprior = (const float*)d_in[2];
    const unsigned char* pmask = (const unsigned char*)d_in[3];
    const float* Wq     = (const float*)d_in[4];
    const float* Wk     = (const float*)d_in[5];
    const float* Wv     = (const float*)d_in[6];
    const float* Th     = (const float*)d_in[7];
    const float* Wfuse  = (const float*)d_in[8];
    const float* W1     = (const float*)d_in[9];
    const float* b1     = (const float*)d_in[10];
    const float* W2     = (const float*)d_in[11];
    const float* b2     = (const float*)d_in[12];
    const float* gamma  = (const float*)d_in[13];
    const float* beta   = (const float*)d_in[14];
    const float* physw  = (const float*)d_in[15];
    const float* priorw = (const float*)d_in[16];
    float* out = (float*)d_out;

    prep_kernel<<<168, 128>>>(Wq, Wk, Wv, Th, W1);

    cudaFuncSetAttribute(fused_gnn_kernel,
                         cudaFuncAttributeMaxDynamicSharedMemorySize, SMEMF * 4);
    fused_gnn_kernel<<<512, TPB, SMEMF * 4>>>(x, edge, Aprior, pmask, Wfuse, W1, b1, W2, b2,
                                              gamma, beta, physw, priorw, out);
}